// round 5
// baseline (speedup 1.0000x reference)
#include <cuda_runtime.h>
#include <cuda_fp16.h>
#include <cstdint>

#define BB 2
#define NSEQ 2048
#define DD 256
#define HH 8
#define DH 32
#define SCALE 0.17677669529663687f  // 1/sqrt(32)

// ---------------- device scratch ----------------
__device__ float g_X[BB * NSEQ * DD];
__device__ float g_T[BB * NSEQ * DD];
__device__ __half g_Xh[BB * NSEQ * DD];
__device__ __half g_Oh[BB * NSEQ * DD];
__device__ __half g_Qh[BB * NSEQ * DD];
__device__ __half g_Kh[BB * NSEQ * DD];
__device__ __half g_Vh[BB * NSEQ * DD];
__device__ float g_RSI[BB * HH * NSEQ];
__device__ __half g_A0[(size_t)BB * NSEQ * NSEQ];
__device__ __half g_A1[(size_t)BB * NSEQ * NSEQ];
__device__ unsigned g_MB[NSEQ * (NSEQ / 32)];
__device__ __half g_Wqh[2 * 256 * 256];
__device__ __half g_Wkh[2 * 256 * 256];
__device__ __half g_Wvh[2 * 256 * 256];
__device__ __half g_Woh[2 * 256 * 256];
__device__ __half g_Wf0h[256 * 256];

// ---------------- asm helpers ----------------
__device__ __forceinline__ unsigned smem_u32(const void* p) {
    return (unsigned)__cvta_generic_to_shared(p);
}
__device__ __forceinline__ void cp16(unsigned dst, const void* src) {
    asm volatile("cp.async.cg.shared.global [%0], [%1], 16;" :: "r"(dst), "l"(src));
}
__device__ __forceinline__ void cp_commit() { asm volatile("cp.async.commit_group;"); }
__device__ __forceinline__ void cp_wait0() { asm volatile("cp.async.wait_group 0;" ::: "memory"); }
__device__ __forceinline__ void cp_wait1() { asm volatile("cp.async.wait_group 1;" ::: "memory"); }

__device__ __forceinline__ void ldm_x4(unsigned d[4], unsigned addr) {
    asm volatile("ldmatrix.sync.aligned.m8n8.x4.shared.b16 {%0,%1,%2,%3}, [%4];"
                 : "=r"(d[0]), "=r"(d[1]), "=r"(d[2]), "=r"(d[3]) : "r"(addr));
}
__device__ __forceinline__ void ldm_x4t(unsigned d[4], unsigned addr) {
    asm volatile("ldmatrix.sync.aligned.m8n8.x4.trans.shared.b16 {%0,%1,%2,%3}, [%4];"
                 : "=r"(d[0]), "=r"(d[1]), "=r"(d[2]), "=r"(d[3]) : "r"(addr));
}
__device__ __forceinline__ void mma_h(float d[4], const unsigned a[4], const unsigned b[2]) {
    asm volatile(
        "mma.sync.aligned.m16n8k16.row.col.f32.f16.f16.f32 "
        "{%0,%1,%2,%3}, {%4,%5,%6,%7}, {%8,%9}, {%0,%1,%2,%3};"
        : "+f"(d[0]), "+f"(d[1]), "+f"(d[2]), "+f"(d[3])
        : "r"(a[0]), "r"(a[1]), "r"(a[2]), "r"(a[3]), "r"(b[0]), "r"(b[1]));
}

// ---------------- multi-array float -> half ----------------
__global__ void k_f2h_multi(
    const float* __restrict__ Wq, const float* __restrict__ Wk,
    const float* __restrict__ Wv, const float* __restrict__ Wo,
    const float* __restrict__ Wf0, const float* __restrict__ x,
    __half* __restrict__ Wqh, __half* __restrict__ Wkh,
    __half* __restrict__ Wvh, __half* __restrict__ Woh,
    __half* __restrict__ Wf0h, __half* __restrict__ xh)
{
    const float* s;
    __half* d;
    int n4;
    switch (blockIdx.y) {
        case 0: s = Wq;  d = Wqh;  n4 = 2 * 65536 / 4; break;
        case 1: s = Wk;  d = Wkh;  n4 = 2 * 65536 / 4; break;
        case 2: s = Wv;  d = Wvh;  n4 = 2 * 65536 / 4; break;
        case 3: s = Wo;  d = Woh;  n4 = 2 * 65536 / 4; break;
        case 4: s = Wf0; d = Wf0h; n4 = 65536 / 4; break;
        default: s = x;  d = xh;   n4 = BB * NSEQ * DD / 4; break;
    }
    int i = blockIdx.x * blockDim.x + threadIdx.x;
    if (i >= n4) return;
    float4 v = *(const float4*)(s + i * 4);
    __half2 a = __floats2half2_rn(v.x, v.y);
    __half2 b = __floats2half2_rn(v.z, v.w);
    uint2 pk;
    pk.x = *(unsigned*)&a;
    pk.y = *(unsigned*)&b;
    *(uint2*)(d + i * 4) = pk;
}

// ---------------- adjacency -> bitmask ----------------
__global__ void k_maskbits(const float* __restrict__ adj, unsigned* __restrict__ mb) {
    int w = blockIdx.x * blockDim.x + threadIdx.x;
    if (w >= NSEQ * (NSEQ / 32)) return;
    int i = w >> 6;
    int c = w & 63;
    const float* row = adj + (size_t)i * NSEQ + c * 32;
    unsigned bits = 0;
#pragma unroll
    for (int t = 0; t < 32; t++) bits |= (row[t] > 0.0f) ? (1u << t) : 0u;
    mb[w] = bits;
}

// ---------------- fp16 tensor-core projection: out[m,n] = sum_k Xin[m,k]*W[n,k] ----------------
#define PJ_STR 40
__global__ __launch_bounds__(256) void k_projh(
    const __half* __restrict__ Xin,
    const __half* __restrict__ W0, const __half* __restrict__ W1, const __half* __restrict__ W2,
    __half* __restrict__ H0, __half* __restrict__ H1, __half* __restrict__ H2,
    float* __restrict__ Fout)
{
    const __half* W = (blockIdx.z == 0) ? W0 : ((blockIdx.z == 1) ? W1 : W2);
    __half* Hc      = (blockIdx.z == 0) ? H0 : ((blockIdx.z == 1) ? H1 : H2);

    __shared__ __half Xs[2][128 * PJ_STR];
    __shared__ __half Ws[2][64 * PJ_STR];

    int m0 = blockIdx.x * 128, n0 = blockIdx.y * 64;
    int t = threadIdx.x, lane = t & 31, warp = t >> 5;
    int wm = warp >> 1, wn = warp & 1;
    int gid = lane >> 2, tig = lane & 3;

    int arow = (lane & 7) + ((lane >> 3) & 1) * 8;
    int acol = (lane >> 4) * 8;
    int brow = (lane & 7) + ((lane >> 4) & 1) * 8;
    int bcol = ((lane >> 3) & 1) * 8;

    float acc[2][4][4] = {};

    auto issue = [&](int buf, int k0) {
#pragma unroll
        for (int l = 0; l < 2; l++) {
            int idx = t + 256 * l;
            int r = idx >> 2, c = (idx & 3) * 8;
            cp16(smem_u32(&Xs[buf][r * PJ_STR + c]), Xin + (size_t)(m0 + r) * DD + k0 + c);
        }
        {
            int r = t >> 2, c = (t & 3) * 8;
            cp16(smem_u32(&Ws[buf][r * PJ_STR + c]), W + (size_t)(n0 + r) * DD + k0 + c);
        }
        cp_commit();
    };

    issue(0, 0);
    for (int kt = 0; kt < 8; kt++) {
        int buf = kt & 1;
        if (kt + 1 < 8) { issue(buf ^ 1, (kt + 1) * 32); cp_wait1(); }
        else cp_wait0();
        __syncthreads();

#pragma unroll
        for (int ks = 0; ks < 32; ks += 16) {
            unsigned af[2][4], bf[2][4];
#pragma unroll
            for (int im = 0; im < 2; im++)
                ldm_x4(af[im], smem_u32(&Xs[buf][(wm * 32 + im * 16 + arow) * PJ_STR + ks + acol]));
#pragma unroll
            for (int p = 0; p < 2; p++)
                ldm_x4(bf[p], smem_u32(&Ws[buf][(wn * 32 + p * 16 + brow) * PJ_STR + ks + bcol]));
#pragma unroll
            for (int im = 0; im < 2; im++) {
                mma_h(acc[im][0], af[im], &bf[0][0]);
                mma_h(acc[im][1], af[im], &bf[0][2]);
                mma_h(acc[im][2], af[im], &bf[1][0]);
                mma_h(acc[im][3], af[im], &bf[1][2]);
            }
        }
        __syncthreads();
    }

#pragma unroll
    for (int im = 0; im < 2; im++) {
        int r0 = m0 + wm * 32 + im * 16 + gid;
#pragma unroll
        for (int in = 0; in < 4; in++) {
            int c0 = n0 + wn * 32 + in * 8 + 2 * tig;
            if (Hc) {
                *(__half2*)(Hc + (size_t)r0 * DD + c0)       = __floats2half2_rn(acc[im][in][0], acc[im][in][1]);
                *(__half2*)(Hc + (size_t)(r0 + 8) * DD + c0) = __floats2half2_rn(acc[im][in][2], acc[im][in][3]);
            }
            if (Fout) {
                *(float2*)(Fout + (size_t)r0 * DD + c0)       = make_float2(acc[im][in][0], acc[im][in][1]);
                *(float2*)(Fout + (size_t)(r0 + 8) * DD + c0) = make_float2(acc[im][in][2], acc[im][in][3]);
            }
        }
    }
}

// ---------------- row sums only: RSI = 1/sum_j exp(masked scores) ----------------
#define QS_STR 40
#define KS_STR 40
__global__ __launch_bounds__(256) void k_rowsum(
    const __half* __restrict__ Qh, const __half* __restrict__ Kh,
    const unsigned* __restrict__ mb, float* __restrict__ RSI)
{
    __shared__ __half Qs[64 * QS_STR];
    __shared__ __half Ks[128 * KS_STR];
    __shared__ float red[64 * 2];

    int bh = blockIdx.y, b = bh >> 3, h = bh & 7;
    int i0 = blockIdx.x * 64;
    int t = threadIdx.x, lane = t & 31, warp = t >> 5;
    int wm = warp & 3, wn = warp >> 2;
    int gid = lane >> 2, tig = lane & 3;

    {
        int row = t >> 2, c = (t & 3) * 8;
        cp16(smem_u32(&Qs[row * QS_STR + c]),
             Qh + ((size_t)(b * NSEQ + i0 + row)) * DD + h * 32 + c);
    }
    cp_commit();

    int arow = wm * 16 + (lane & 7) + ((lane >> 3) & 1) * 8;
    int acol = (lane >> 4) * 8;
    unsigned aBase = smem_u32(&Qs[arow * QS_STR + acol]);
    int brow = (lane & 7) + ((lane >> 4) & 1) * 8;
    int bcol = ((lane >> 3) & 1) * 8;

    float sA = 0.f, sB = 0.f;
    int gi_a = i0 + wm * 16 + gid;
    int gi_b = gi_a + 8;

    for (int jc = 0; jc < 16; jc++) {
        int j0 = jc * 128;
#pragma unroll
        for (int l = 0; l < 2; l++) {
            int idx = t + 256 * l;
            int row = idx >> 2, c = (idx & 3) * 8;
            cp16(smem_u32(&Ks[row * KS_STR + c]),
                 Kh + ((size_t)(b * NSEQ + j0 + row)) * DD + h * 32 + c);
        }
        cp_commit();
        cp_wait0();
        __syncthreads();

        float acc[8][4] = {};
#pragma unroll
        for (int d0 = 0; d0 < 32; d0 += 16) {
            unsigned a[4];
            ldm_x4(a, aBase + d0 * 2);
#pragma unroll
            for (int p = 0; p < 4; p++) {
                unsigned bb[4];
                ldm_x4(bb, smem_u32(&Ks[(wn * 64 + p * 16 + brow) * KS_STR + bcol + d0]));
                mma_h(acc[2 * p],     a, &bb[0]);
                mma_h(acc[2 * p + 1], a, &bb[2]);
            }
        }

        const unsigned* mba = &mb[gi_a * 64];
        const unsigned* mbb = &mb[gi_b * 64];
#pragma unroll
        for (int in = 0; in < 8; in++) {
            int gj = j0 + wn * 64 + in * 8 + 2 * tig;
            unsigned wa = mba[gj >> 5], wb = mbb[gj >> 5];
            int sh = gj & 31;
            if ((wa >> sh) & 1u)       sA += __expf(acc[in][0] * SCALE);
            if ((wa >> (sh + 1)) & 1u) sA += __expf(acc[in][1] * SCALE);
            if ((wb >> sh) & 1u)       sB += __expf(acc[in][2] * SCALE);
            if ((wb >> (sh + 1)) & 1u) sB += __expf(acc[in][3] * SCALE);
        }
        __syncthreads();
    }

    sA += __shfl_xor_sync(0xffffffffu, sA, 1);
    sA += __shfl_xor_sync(0xffffffffu, sA, 2);
    sB += __shfl_xor_sync(0xffffffffu, sB, 1);
    sB += __shfl_xor_sync(0xffffffffu, sB, 2);
    if (tig == 0) {
        red[(wm * 16 + gid) * 2 + wn]     = sA;
        red[(wm * 16 + gid + 8) * 2 + wn] = sB;
    }
    __syncthreads();
    if (t < 64)
        RSI[bh * NSEQ + i0 + t] = 1.0f / (red[t * 2] + red[t * 2 + 1]);
}

// ---------------- fused attention: recompute E in smem, emit O + A, no E in DRAM ----------------
// block (b, 32 q rows), 512 threads = 16 warps, warp = (head h, row-half s).
#define AT_STR 264
#define AT_ES_STR 72
#define AT_Q_HALFS (32 * AT_STR)
#define AT_KV_HALFS (64 * AT_STR)
#define AT_ES_HALFS (256 * AT_ES_STR)
#define ATTN_SMEM ((AT_Q_HALFS + 4 * AT_KV_HALFS + AT_ES_HALFS) * 2 + 256 * 4)

__global__ __launch_bounds__(512) void k_attn(
    const __half* __restrict__ Qh, const __half* __restrict__ Kh,
    const __half* __restrict__ Vh,
    const unsigned* __restrict__ mb, const float* __restrict__ RSI,
    __half* __restrict__ Oh, __half* __restrict__ A)
{
    extern __shared__ __half sm[];
    __half* Qs = sm;
    __half* Ks = Qs + AT_Q_HALFS;            // 2 bufs
    __half* Vs = Ks + 2 * AT_KV_HALFS;       // 2 bufs
    __half* Es = Vs + 2 * AT_KV_HALFS;
    float* ws = (float*)(Es + AT_ES_HALFS);

    int b = blockIdx.y, i0 = blockIdx.x * 32;
    int t = threadIdx.x, lane = t & 31, warp = t >> 5;
    int h = warp >> 1, s = warp & 1;
    int gid = lane >> 2, tig = lane & 3;

    if (t < 256) ws[t] = RSI[(b * HH + (t >> 5)) * NSEQ + i0 + (t & 31)];

    // load Q tile: 32 rows x 256 halfs
#pragma unroll
    for (int l = 0; l < 2; l++) {
        int idx = t + 512 * l;
        int row = idx >> 5, c = (idx & 31) * 8;
        cp16(smem_u32(&Qs[row * AT_STR + c]),
             Qh + ((size_t)(b * NSEQ + i0 + row)) * DD + c);
    }

    auto issueKV = [&](int buf, int j0) {
#pragma unroll
        for (int l = 0; l < 4; l++) {
            int idx = t + 512 * l;
            int row = idx >> 5, c = (idx & 31) * 8;
            cp16(smem_u32(&Ks[buf * AT_KV_HALFS + row * AT_STR + c]),
                 Kh + ((size_t)(b * NSEQ + j0 + row)) * DD + c);
            cp16(smem_u32(&Vs[buf * AT_KV_HALFS + row * AT_STR + c]),
                 Vh + ((size_t)(b * NSEQ + j0 + row)) * DD + c);
        }
        cp_commit();
    };
    issueKV(0, 0);   // Q + KV0 in one group

    int arow = (lane & 7) + ((lane >> 3) & 1) * 8;
    int acol = (lane >> 4) * 8;
    int brow_qk = (lane & 7) + ((lane >> 4) & 1) * 8;
    int bcol_qk = ((lane >> 3) & 1) * 8;
    int brow_pv = (lane & 7) + ((lane >> 3) & 1) * 8;
    int bcol_pv = (lane >> 4) * 8;

    int gi_a = i0 + s * 16 + gid;
    int gi_b = gi_a + 8;
    int erA = h * 32 + s * 16 + gid;
    int aggrow = t >> 4, aggcol = (t & 15) * 4;

    float oacc[4][4] = {};

    for (int jt = 0; jt < 32; jt++) {
        int buf = jt & 1;
        int j0 = jt * 64;
        if (jt + 1 < 32) { issueKV(buf ^ 1, (jt + 1) * 64); cp_wait1(); }
        else cp_wait0();
        __syncthreads();

        __half* kb = Ks + buf * AT_KV_HALFS;
        __half* vb = Vs + buf * AT_KV_HALFS;

        // QK mma: rows s*16..+15 of head h, all 64 j
        float eacc[8][4] = {};
#pragma unroll
        for (int ks = 0; ks < 32; ks += 16) {
            unsigned a[4];
            ldm_x4(a, smem_u32(&Qs[(s * 16 + arow) * AT_STR + h * 32 + ks + acol]));
#pragma unroll
            for (int p = 0; p < 4; p++) {
                unsigned bb[4];
                ldm_x4(bb, smem_u32(&kb[(p * 16 + brow_qk) * AT_STR + h * 32 + ks + bcol_qk]));
                mma_h(eacc[2 * p],     a, &bb[0]);
                mma_h(eacc[2 * p + 1], a, &bb[2]);
            }
        }

        // exp + mask -> Es
        const unsigned* mba = &mb[gi_a * 64];
        const unsigned* mbb = &mb[gi_b * 64];
#pragma unroll
        for (int in = 0; in < 8; in++) {
            int col = in * 8 + 2 * tig;
            int gj = j0 + col;
            unsigned wa = mba[gj >> 5], wb = mbb[gj >> 5];
            int sh = gj & 31;
            float e0 = ((wa >> sh) & 1u)       ? __expf(eacc[in][0] * SCALE) : 0.f;
            float e1 = ((wa >> (sh + 1)) & 1u) ? __expf(eacc[in][1] * SCALE) : 0.f;
            float e2 = ((wb >> sh) & 1u)       ? __expf(eacc[in][2] * SCALE) : 0.f;
            float e3 = ((wb >> (sh + 1)) & 1u) ? __expf(eacc[in][3] * SCALE) : 0.f;
            *(__half2*)&Es[erA * AT_ES_STR + col]       = __floats2half2_rn(e0, e1);
            *(__half2*)&Es[(erA + 8) * AT_ES_STR + col] = __floats2half2_rn(e2, e3);
        }
        __syncthreads();

        // head-averaged A tile: 32 rows x 64 cols
        {
            float a0 = 0, a1 = 0, a2 = 0, a3 = 0;
#pragma unroll
            for (int hh = 0; hh < 8; hh++) {
                float w = ws[hh * 32 + aggrow];
                float2 f0 = __half22float2(*(__half2*)&Es[(hh * 32 + aggrow) * AT_ES_STR + aggcol]);
                float2 f1 = __half22float2(*(__half2*)&Es[(hh * 32 + aggrow) * AT_ES_STR + aggcol + 2]);
                a0 += w * f0.x; a1 += w * f0.y; a2 += w * f1.x; a3 += w * f1.y;
            }
            __half2 o0 = __floats2half2_rn(a0 * 0.125f, a1 * 0.125f);
            __half2 o1 = __floats2half2_rn(a2 * 0.125f, a3 * 0.125f);
            uint2 pk;
            pk.x = *(unsigned*)&o0;
            pk.y = *(unsigned*)&o1;
            *(uint2*)(A + ((size_t)b * NSEQ + i0 + aggrow) * NSEQ + j0 + aggcol) = pk;
        }

        // PV mma
#pragma unroll
        for (int ks = 0; ks < 64; ks += 16) {
            unsigned a[4];
            ldm_x4(a, smem_u32(&Es[(h * 32 + s * 16 + arow) * AT_ES_STR + ks + acol]));
#pragma unroll
            for (int p = 0; p < 2; p++) {
                unsigned bb[4];
                ldm_x4t(bb, smem_u32(&vb[(ks + brow_pv) * AT_STR + h * 32 + p * 16 + bcol_pv]));
                mma_h(oacc[2 * p],     a, &bb[0]);
                mma_h(oacc[2 * p + 1], a, &bb[2]);
            }
        }
        __syncthreads();
    }

    int r0 = s * 16 + gid;
    float w0 = ws[h * 32 + r0];
    float w1 = ws[h * 32 + r0 + 8];
#pragma unroll
    for (int in = 0; in < 4; in++) {
        int c0 = h * 32 + in * 8 + 2 * tig;
        size_t base = ((size_t)(b * NSEQ + i0 + r0)) * DD + c0;
        *(__half2*)(Oh + base)          = __floats2half2_rn(oacc[in][0] * w0, oacc[in][1] * w0);
        *(__half2*)(Oh + base + 8 * DD) = __floats2half2_rn(oacc[in][2] * w1, oacc[in][3] * w1);
    }
}

// ---------------- residual + layernorm (in place on X, mirrors to Xh) ----------------
__global__ void k_addln(float* __restrict__ X, __half* __restrict__ Xh,
                        const float* __restrict__ T,
                        const float* __restrict__ g, const float* __restrict__ bta)
{
    int row = blockIdx.x;
    int t = threadIdx.x;
    float v = X[row * 256 + t] + T[row * 256 + t];
    float s = v, s2 = v * v;
#pragma unroll
    for (int off = 16; off > 0; off >>= 1) {
        s  += __shfl_xor_sync(0xffffffffu, s, off);
        s2 += __shfl_xor_sync(0xffffffffu, s2, off);
    }
    __shared__ float red[16];
    __shared__ float mu_s, rstd_s;
    int w = t >> 5, lane = t & 31;
    if (lane == 0) { red[w] = s; red[8 + w] = s2; }
    __syncthreads();
    if (t == 0) {
        float S = 0.f, S2 = 0.f;
#pragma unroll
        for (int i = 0; i < 8; i++) { S += red[i]; S2 += red[8 + i]; }
        float mu = S * (1.0f / 256.0f);
        float var = S2 * (1.0f / 256.0f) - mu * mu;
        mu_s = mu;
        rstd_s = rsqrtf(var + 1e-5f);
    }
    __syncthreads();
    float r = (v - mu_s) * rstd_s * g[t] + bta[t];
    X[row * 256 + t] = r;
    Xh[row * 256 + t] = __float2half_rn(r);
}

// ---------------- chain GEMM via fp16 mma, cp.async double-buffered ----------------
#define CH_AS_STR 72
#define CH_BS_STR 136
#define CH_AS_HALFS (128 * CH_AS_STR)
#define CH_BS_HALFS (64 * CH_BS_STR)
#define CHAIN_SMEM ((2 * CH_AS_HALFS + 2 * CH_BS_HALFS) * 2)

__global__ __launch_bounds__(256, 2) void k_chain_h(
    const __half* __restrict__ A, const __half* __restrict__ B, float* __restrict__ C)
{
    extern __shared__ __half chs[];
    __half* AsB = chs;
    __half* BsB = chs + 2 * CH_AS_HALFS;

    int bb = blockIdx.z;
    const __half* Ab = A + (size_t)bb * NSEQ * NSEQ;
    const __half* Bb = B + (size_t)bb * NSEQ * NSEQ;
    float* Cb = C + (size_t)bb * NSEQ * NSEQ;

    int t = threadIdx.x, lane = t & 31, warp = t >> 5;
    int wm = warp >> 2, wn = warp & 3;
    int gid = lane >> 2, tig = lane & 3;
    int m0 = blockIdx.y * 128, n0 = blockIdx.x * 128;

    int arow = (lane & 7) + ((lane >> 3) & 1) * 8;
    int acol = (lane >> 4) * 8;
    int brow = (lane & 7) + ((lane >> 3) & 1) * 8;
    int bcol = (lane >> 4) * 8;

    float acc[4][4][4] = {};

    auto issue = [&](int buf, int k0) {
        __half* as = AsB + buf * CH_AS_HALFS;
        __half* bs = BsB + buf * CH_BS_HALFS;
#pragma unroll
        for (int l = 0; l < 4; l++) {
            int idx = t + 256 * l;
            int r = idx >> 3, c = (idx & 7) * 8;
            cp16(smem_u32(&as[r * CH_AS_STR + c]), Ab + (size_t)(m0 + r) * NSEQ + k0 + c);
        }
#pragma unroll
        for (int l = 0; l < 4; l++) {
            int idx = t + 256 * l;
            int r = idx >> 4, c = (idx & 15) * 8;
            cp16(smem_u32(&bs[r * CH_BS_STR + c]), Bb + (size_t)(k0 + r) * NSEQ + n0 + c);
        }
        cp_commit();
    };

    issue(0, 0);
    for (int kt = 0; kt < 32; kt++) {
        int buf = kt & 1;
        if (kt + 1 < 32) {
            issue(buf ^ 1, (kt + 1) * 64);
            cp_wait1();
        } else {
            cp_wait0();
        }
        __syncthreads();

        __half* as = AsB + buf * CH_AS_HALFS;
        __half* bs = BsB + buf * CH_BS_HALFS;
#pragma unroll
        for (int ks = 0; ks < 64; ks += 16) {
            unsigned af[4][4], bf[2][4];
#pragma unroll
            for (int im = 0; im < 4; im++)
                ldm_x4(af[im], smem_u32(&as[(wm * 64 + im * 16 + arow) * CH_AS_STR + ks + acol]));
#pragma unroll
            for (int p = 0; p < 2; p++)
                ldm_x4t(bf[p], smem_u32(&bs[(ks + brow) * CH_BS_STR + wn * 32 + p * 16 + bcol]));
#pragma unroll
            for (int im = 0; im < 4; im++) {
                mma_h(acc[im][0], af[im], &bf[0][0]);
                mma_h(acc[im][1], af[im], &bf[0][2]);
                mma_h(acc[im][2], af[im], &bf[1][0]);
                mma_h(acc[im][3], af[im], &bf[1][2]);
            }
        }
        __syncthreads();
    }

#pragma unroll
    for (int im = 0; im < 4; im++) {
        int r0 = m0 + wm * 64 + im * 16 + gid;
#pragma unroll
        for (int in = 0; in < 4; in++) {
            int c0 = n0 + wn * 32 + in * 8 + 2 * tig;
            *(float2*)(Cb + (size_t)r0 * NSEQ + c0)       = make_float2(acc[im][in][0], acc[im][in][1]);
            *(float2*)(Cb + (size_t)(r0 + 8) * NSEQ + c0) = make_float2(acc[im][in][2], acc[im][in][3]);
        }
    }
}

// ---------------- host ----------------
extern "C" void kernel_launch(void* const* d_in, const int* in_sizes, int n_in,
                              void* d_out, int out_size)
{
    const float* x     = (const float*)d_in[0];
    const float* adj   = (const float*)d_in[1];
    const float* Wf0   = (const float*)d_in[2];
    const float* Wq    = (const float*)d_in[3];
    const float* Wk    = (const float*)d_in[4];
    const float* Wv    = (const float*)d_in[5];
    const float* Wo    = (const float*)d_in[6];
    const float* gamma = (const float*)d_in[7];
    const float* beta  = (const float*)d_in[8];
    float* out_x    = (float*)d_out;
    float* out_attn = (float*)d_out + (size_t)BB * NSEQ * DD;

    float *X, *T, *RSI;
    __half *Xh, *Oh, *Qh, *Kh, *Vh, *A0, *A1;
    __half *Wqh, *Wkh, *Wvh, *Woh, *Wf0h;
    unsigned* MB;
    cudaGetSymbolAddress((void**)&X, g_X);
    cudaGetSymbolAddress((void**)&T, g_T);
    cudaGetSymbolAddress((void**)&Xh, g_Xh);
    cudaGetSymbolAddress((void**)&Oh, g_Oh);
    cudaGetSymbolAddress((void**)&Qh, g_Qh);
    cudaGetSymbolAddress((void**)&Kh, g_Kh);
    cudaGetSymbolAddress((void**)&Vh, g_Vh);
    cudaGetSymbolAddress((void**)&RSI, g_RSI);
    cudaGetSymbolAddress((void**)&A0, g_A0);
    cudaGetSymbolAddress((void**)&A1, g_A1);
    cudaGetSymbolAddress((void**)&MB, g_MB);
    cudaGetSymbolAddress((void**)&Wqh, g_Wqh);
    cudaGetSymbolAddress((void**)&Wkh, g_Wkh);
    cudaGetSymbolAddress((void**)&Wvh, g_Wvh);
    cudaGetSymbolAddress((void**)&Woh, g_Woh);
    cudaGetSymbolAddress((void**)&Wf0h, g_Wf0h);

    cudaFuncSetAttribute(k_attn, cudaFuncAttributeMaxDynamicSharedMemorySize, ATTN_SMEM);
    cudaFuncSetAttribute(k_chain_h, cudaFuncAttributeMaxDynamicSharedMemorySize, CHAIN_SMEM);

    const int WSZ = 256 * 256;

    k_maskbits<<<512, 256>>>(adj, MB);
    // convert all weights + x to half (x temp -> Qh buffer)
    k_f2h_multi<<<dim3(1024, 6), 256>>>(Wq, Wk, Wv, Wo, Wf0, x,
                                        Wqh, Wkh, Wvh, Woh, Wf0h, Qh);

    // f0: X/Xh = x @ Wf0^T (fp16 tensor cores, fp32 + half outputs)
    k_projh<<<dim3(32, 4, 1), 256>>>(Qh, Wf0h, Wf0h, Wf0h, Xh, Xh, Xh, X);

    for (int i = 0; i < 2; i++) {
        k_projh<<<dim3(32, 4, 3), 256>>>(Xh, Wqh + i * WSZ, Wkh + i * WSZ, Wvh + i * WSZ,
                                         Qh, Kh, Vh, (float*)nullptr);
        k_rowsum<<<dim3(NSEQ / 64, BB * HH), 256>>>(Qh, Kh, MB, RSI);
        k_attn<<<dim3(NSEQ / 32, BB), 512, ATTN_SMEM>>>(Qh, Kh, Vh, MB, RSI,
                                                        Oh, (i == 0) ? A0 : A1);
        k_projh<<<dim3(32, 4, 1), 256>>>(Oh, Woh + i * WSZ, Woh + i * WSZ, Woh + i * WSZ,
                                         (half*)nullptr, (half*)nullptr, (half*)nullptr, T);
        k_addln<<<BB * NSEQ, 256>>>(X, Xh, T, gamma + i * 256, beta + i * 256);
    }

    k_chain_h<<<dim3(NSEQ / 128, NSEQ / 128, BB), 256, CHAIN_SMEM>>>(A1, A0, out_attn);

    cudaMemcpyAsync(out_x, X, (size_t)BB * NSEQ * DD * sizeof(float),
                    cudaMemcpyDeviceToDevice);
}

// round 7
// speedup vs baseline: 1.1579x; 1.1579x over previous
#include <cuda_runtime.h>
#include <cuda_fp16.h>
#include <cstdint>

#define BB 2
#define NSEQ 2048
#define DD 256
#define HH 8
#define DH 32
#define SCALE 0.17677669529663687f  // 1/sqrt(32)

// ---------------- device scratch ----------------
__device__ float g_X[BB * NSEQ * DD];
__device__ float g_T[BB * NSEQ * DD];
__device__ __half g_Xh[BB * NSEQ * DD];
__device__ __half g_Oh[BB * NSEQ * DD];
__device__ __half g_Qh[BB * NSEQ * DD];
__device__ __half g_Kh[BB * NSEQ * DD];
__device__ __half g_Vh[BB * NSEQ * DD];
__device__ __half g_Eh[(size_t)BB * HH * NSEQ * NSEQ];   // exp(masked scores), unnormalized, half
__device__ float g_RSI[BB * HH * NSEQ];
__device__ __half g_A0[(size_t)BB * NSEQ * NSEQ];
__device__ __half g_A1[(size_t)BB * NSEQ * NSEQ];
__device__ unsigned g_MB[NSEQ * (NSEQ / 32)];
__device__ __half g_Wqh[2 * 256 * 256];
__device__ __half g_Wkh[2 * 256 * 256];
__device__ __half g_Wvh[2 * 256 * 256];
__device__ __half g_Woh[2 * 256 * 256];
__device__ __half g_Wf0h[256 * 256];

// ---------------- asm helpers ----------------
__device__ __forceinline__ unsigned smem_u32(const void* p) {
    return (unsigned)__cvta_generic_to_shared(p);
}
__device__ __forceinline__ void cp16(unsigned dst, const void* src) {
    asm volatile("cp.async.cg.shared.global [%0], [%1], 16;" :: "r"(dst), "l"(src));
}
__device__ __forceinline__ void cp_commit() { asm volatile("cp.async.commit_group;"); }
__device__ __forceinline__ void cp_wait0() { asm volatile("cp.async.wait_group 0;" ::: "memory"); }
__device__ __forceinline__ void cp_wait1() { asm volatile("cp.async.wait_group 1;" ::: "memory"); }

__device__ __forceinline__ void ldm_x4(unsigned d[4], unsigned addr) {
    asm volatile("ldmatrix.sync.aligned.m8n8.x4.shared.b16 {%0,%1,%2,%3}, [%4];"
                 : "=r"(d[0]), "=r"(d[1]), "=r"(d[2]), "=r"(d[3]) : "r"(addr));
}
__device__ __forceinline__ void ldm_x4t(unsigned d[4], unsigned addr) {
    asm volatile("ldmatrix.sync.aligned.m8n8.x4.trans.shared.b16 {%0,%1,%2,%3}, [%4];"
                 : "=r"(d[0]), "=r"(d[1]), "=r"(d[2]), "=r"(d[3]) : "r"(addr));
}
__device__ __forceinline__ void mma_h(float d[4], const unsigned a[4], const unsigned b[2]) {
    asm volatile(
        "mma.sync.aligned.m16n8k16.row.col.f32.f16.f16.f32 "
        "{%0,%1,%2,%3}, {%4,%5,%6,%7}, {%8,%9}, {%0,%1,%2,%3};"
        : "+f"(d[0]), "+f"(d[1]), "+f"(d[2]), "+f"(d[3])
        : "r"(a[0]), "r"(a[1]), "r"(a[2]), "r"(a[3]), "r"(b[0]), "r"(b[1]));
}

// ---------------- multi-array float -> half ----------------
__global__ void k_f2h_multi(
    const float* __restrict__ Wq, const float* __restrict__ Wk,
    const float* __restrict__ Wv, const float* __restrict__ Wo,
    const float* __restrict__ Wf0, const float* __restrict__ x,
    __half* __restrict__ Wqh, __half* __restrict__ Wkh,
    __half* __restrict__ Wvh, __half* __restrict__ Woh,
    __half* __restrict__ Wf0h, __half* __restrict__ xh)
{
    const float* s;
    __half* d;
    int n4;
    switch (blockIdx.y) {
        case 0: s = Wq;  d = Wqh;  n4 = 2 * 65536 / 4; break;
        case 1: s = Wk;  d = Wkh;  n4 = 2 * 65536 / 4; break;
        case 2: s = Wv;  d = Wvh;  n4 = 2 * 65536 / 4; break;
        case 3: s = Wo;  d = Woh;  n4 = 2 * 65536 / 4; break;
        case 4: s = Wf0; d = Wf0h; n4 = 65536 / 4; break;
        default: s = x;  d = xh;   n4 = BB * NSEQ * DD / 4; break;
    }
    int i = blockIdx.x * blockDim.x + threadIdx.x;
    if (i >= n4) return;
    float4 v = *(const float4*)(s + i * 4);
    __half2 a = __floats2half2_rn(v.x, v.y);
    __half2 b = __floats2half2_rn(v.z, v.w);
    uint2 pk;
    pk.x = *(unsigned*)&a;
    pk.y = *(unsigned*)&b;
    *(uint2*)(d + i * 4) = pk;
}

// ---------------- adjacency -> bitmask ----------------
__global__ void k_maskbits(const float* __restrict__ adj, unsigned* __restrict__ mb) {
    int w = blockIdx.x * blockDim.x + threadIdx.x;
    if (w >= NSEQ * (NSEQ / 32)) return;
    int i = w >> 6;
    int c = w & 63;
    const float* row = adj + (size_t)i * NSEQ + c * 32;
    unsigned bits = 0;
#pragma unroll
    for (int t = 0; t < 32; t++) bits |= (row[t] > 0.0f) ? (1u << t) : 0u;
    mb[w] = bits;
}

// ---------------- fp16 tensor-core projection: out[m,n] = sum_k Xin[m,k]*W[n,k] ----------------
#define PJ_STR 40
__global__ __launch_bounds__(256) void k_projh(
    const __half* __restrict__ Xin,
    const __half* __restrict__ W0, const __half* __restrict__ W1, const __half* __restrict__ W2,
    __half* __restrict__ H0, __half* __restrict__ H1, __half* __restrict__ H2,
    float* __restrict__ Fout)
{
    const __half* W = (blockIdx.z == 0) ? W0 : ((blockIdx.z == 1) ? W1 : W2);
    __half* Hc      = (blockIdx.z == 0) ? H0 : ((blockIdx.z == 1) ? H1 : H2);

    __shared__ __half Xs[2][128 * PJ_STR];
    __shared__ __half Ws[2][64 * PJ_STR];

    int m0 = blockIdx.x * 128, n0 = blockIdx.y * 64;
    int t = threadIdx.x, lane = t & 31, warp = t >> 5;
    int wm = warp >> 1, wn = warp & 1;
    int gid = lane >> 2, tig = lane & 3;

    int arow = (lane & 7) + ((lane >> 3) & 1) * 8;
    int acol = (lane >> 4) * 8;
    int brow = (lane & 7) + ((lane >> 4) & 1) * 8;
    int bcol = ((lane >> 3) & 1) * 8;

    float acc[2][4][4] = {};

    auto issue = [&](int buf, int k0) {
#pragma unroll
        for (int l = 0; l < 2; l++) {
            int idx = t + 256 * l;
            int r = idx >> 2, c = (idx & 3) * 8;
            cp16(smem_u32(&Xs[buf][r * PJ_STR + c]), Xin + (size_t)(m0 + r) * DD + k0 + c);
        }
        {
            int r = t >> 2, c = (t & 3) * 8;
            cp16(smem_u32(&Ws[buf][r * PJ_STR + c]), W + (size_t)(n0 + r) * DD + k0 + c);
        }
        cp_commit();
    };

    issue(0, 0);
    for (int kt = 0; kt < 8; kt++) {
        int buf = kt & 1;
        if (kt + 1 < 8) { issue(buf ^ 1, (kt + 1) * 32); cp_wait1(); }
        else cp_wait0();
        __syncthreads();

#pragma unroll
        for (int ks = 0; ks < 32; ks += 16) {
            unsigned af[2][4], bf[2][4];
#pragma unroll
            for (int im = 0; im < 2; im++)
                ldm_x4(af[im], smem_u32(&Xs[buf][(wm * 32 + im * 16 + arow) * PJ_STR + ks + acol]));
#pragma unroll
            for (int p = 0; p < 2; p++)
                ldm_x4(bf[p], smem_u32(&Ws[buf][(wn * 32 + p * 16 + brow) * PJ_STR + ks + bcol]));
#pragma unroll
            for (int im = 0; im < 2; im++) {
                mma_h(acc[im][0], af[im], &bf[0][0]);
                mma_h(acc[im][1], af[im], &bf[0][2]);
                mma_h(acc[im][2], af[im], &bf[1][0]);
                mma_h(acc[im][3], af[im], &bf[1][2]);
            }
        }
        __syncthreads();
    }

#pragma unroll
    for (int im = 0; im < 2; im++) {
        int r0 = m0 + wm * 32 + im * 16 + gid;
#pragma unroll
        for (int in = 0; in < 4; in++) {
            int c0 = n0 + wn * 32 + in * 8 + 2 * tig;
            if (Hc) {
                *(__half2*)(Hc + (size_t)r0 * DD + c0)       = __floats2half2_rn(acc[im][in][0], acc[im][in][1]);
                *(__half2*)(Hc + (size_t)(r0 + 8) * DD + c0) = __floats2half2_rn(acc[im][in][2], acc[im][in][3]);
            }
            if (Fout) {
                *(float2*)(Fout + (size_t)r0 * DD + c0)       = make_float2(acc[im][in][0], acc[im][in][1]);
                *(float2*)(Fout + (size_t)(r0 + 8) * DD + c0) = make_float2(acc[im][in][2], acc[im][in][3]);
            }
        }
    }
}

// ---------------- scores via fp16 mma + mask + exp + rowsum -> E half ----------------
// double-buffered K tiles; E staged in smem for coalesced stores
#define QS_STR 40
#define KS_STR 40
#define ES_STR 136
__global__ __launch_bounds__(256) void k_scores(
    const __half* __restrict__ Qh, const __half* __restrict__ Kh,
    const unsigned* __restrict__ mb,
    __half* __restrict__ Eh, float* __restrict__ RSI)
{
    __shared__ __half Qs[64 * QS_STR];
    __shared__ __half Ks[2][128 * KS_STR];
    __shared__ __half Es[64 * ES_STR];
    __shared__ float red[64 * 2];

    int bh = blockIdx.y, b = bh >> 3, h = bh & 7;
    int i0 = blockIdx.x * 64;
    int t = threadIdx.x, lane = t & 31, warp = t >> 5;
    int wm = warp & 3, wn = warp >> 2;
    int gid = lane >> 2, tig = lane & 3;

    // Q tile (issued together with first K group)
    {
        int row = t >> 2, c = (t & 3) * 8;
        cp16(smem_u32(&Qs[row * QS_STR + c]),
             Qh + ((size_t)(b * NSEQ + i0 + row)) * DD + h * 32 + c);
    }
    auto issueK = [&](int buf, int j0) {
#pragma unroll
        for (int l = 0; l < 2; l++) {
            int idx = t + 256 * l;
            int row = idx >> 2, c = (idx & 3) * 8;
            cp16(smem_u32(&Ks[buf][row * KS_STR + c]),
                 Kh + ((size_t)(b * NSEQ + j0 + row)) * DD + h * 32 + c);
        }
        cp_commit();
    };
    issueK(0, 0);

    int arow = wm * 16 + (lane & 7) + ((lane >> 3) & 1) * 8;
    int acol = (lane >> 4) * 8;
    unsigned aBase = smem_u32(&Qs[arow * QS_STR + acol]);
    int brow = (lane & 7) + ((lane >> 4) & 1) * 8;
    int bcol = ((lane >> 3) & 1) * 8;

    float sA = 0.f, sB = 0.f;
    int gi_a = i0 + wm * 16 + gid;
    int gi_b = gi_a + 8;
    int lrowA = wm * 16 + gid;

    for (int jc = 0; jc < 16; jc++) {
        int buf = jc & 1;
        int j0 = jc * 128;
        if (jc + 1 < 16) { issueK(buf ^ 1, (jc + 1) * 128); cp_wait1(); }
        else cp_wait0();
        __syncthreads();

        float acc[8][4] = {};
#pragma unroll
        for (int d0 = 0; d0 < 32; d0 += 16) {
            unsigned a[4];
            ldm_x4(a, aBase + d0 * 2);
#pragma unroll
            for (int p = 0; p < 4; p++) {
                unsigned bb[4];
                ldm_x4(bb, smem_u32(&Ks[buf][(wn * 64 + p * 16 + brow) * KS_STR + bcol + d0]));
                mma_h(acc[2 * p],     a, &bb[0]);
                mma_h(acc[2 * p + 1], a, &bb[2]);
            }
        }

        const unsigned* mba = &mb[gi_a * 64];
        const unsigned* mbb = &mb[gi_b * 64];
#pragma unroll
        for (int in = 0; in < 8; in++) {
            int col = wn * 64 + in * 8 + 2 * tig;
            int gj = j0 + col;
            unsigned wa = mba[gj >> 5], wb = mbb[gj >> 5];
            int sh = gj & 31;
            float e0 = ((wa >> sh) & 1u)       ? __expf(acc[in][0] * SCALE) : 0.f;
            float e1 = ((wa >> (sh + 1)) & 1u) ? __expf(acc[in][1] * SCALE) : 0.f;
            float e2 = ((wb >> sh) & 1u)       ? __expf(acc[in][2] * SCALE) : 0.f;
            float e3 = ((wb >> (sh + 1)) & 1u) ? __expf(acc[in][3] * SCALE) : 0.f;
            sA += e0 + e1;
            sB += e2 + e3;
            *(__half2*)&Es[lrowA * ES_STR + col]       = __floats2half2_rn(e0, e1);
            *(__half2*)&Es[(lrowA + 8) * ES_STR + col] = __floats2half2_rn(e2, e3);
        }
        __syncthreads();
        // coalesced copy-out: 64 rows x 128 halfs = 1024 x 16B
#pragma unroll
        for (int l = 0; l < 4; l++) {
            int id = t + 256 * l;
            int row = id >> 4, cc = (id & 15) * 8;
            uint4 v = *(uint4*)&Es[row * ES_STR + cc];
            *(uint4*)(Eh + ((size_t)bh * NSEQ + i0 + row) * NSEQ + j0 + cc) = v;
        }
        __syncthreads();
    }

    sA += __shfl_xor_sync(0xffffffffu, sA, 1);
    sA += __shfl_xor_sync(0xffffffffu, sA, 2);
    sB += __shfl_xor_sync(0xffffffffu, sB, 1);
    sB += __shfl_xor_sync(0xffffffffu, sB, 2);
    if (tig == 0) {
        red[(wm * 16 + gid) * 2 + wn]     = sA;
        red[(wm * 16 + gid + 8) * 2 + wn] = sB;
    }
    __syncthreads();
    if (t < 64)
        RSI[bh * NSEQ + i0 + t] = 1.0f / (red[t * 2] + red[t * 2 + 1]);
}

// ---------------- fused PV (fp16 mma) + head-averaged attention, double-buffered ----------------
#define PV_ES_STR 72
#define PV_VS_STR 264
#define PV_ES_HALFS (256 * PV_ES_STR)
#define PV_VS_HALFS (64 * PV_VS_STR)
#define PVAGG_SMEM ((2 * PV_ES_HALFS + 2 * PV_VS_HALFS) * 2 + 256 * 4)

__global__ __launch_bounds__(512) void k_pvagg(
    const __half* __restrict__ Eh, const float* __restrict__ RSI,
    const __half* __restrict__ Vh, __half* __restrict__ Oh, __half* __restrict__ A)
{
    extern __shared__ __half smh[];
    __half* EsB = smh;                        // 2 bufs
    __half* VsB = smh + 2 * PV_ES_HALFS;      // 2 bufs
    float* ws = (float*)(VsB + 2 * PV_VS_HALFS);

    int b = blockIdx.y, i0 = blockIdx.x * 32;
    int t = threadIdx.x, lane = t & 31, warp = t >> 5;
    int h = warp >> 1, s = warp & 1;
    int gid = lane >> 2, tig = lane & 3;

    if (t < 256) ws[t] = RSI[(b * HH + (t >> 5)) * NSEQ + i0 + (t & 31)];

    int arow = (lane & 7) + ((lane >> 3) & 1) * 8;
    int acol = (lane >> 4) * 8;
    int brow = (lane & 7) + ((lane >> 3) & 1) * 8;
    int bcol = (lane >> 4) * 8;
    int er0 = h * 32 + s * 16;

    int ai = t >> 4, aj = (t & 15) * 4;

    auto issueEV = [&](int buf, int j0) {
        __half* Es = EsB + buf * PV_ES_HALFS;
        __half* Vs = VsB + buf * PV_VS_HALFS;
#pragma unroll
        for (int l = 0; l < 4; l++) {
            int idx = t + 512 * l;
            int row = idx >> 3, c = (idx & 7) * 8;
            int eh = row >> 5, ei = row & 31;
            cp16(smem_u32(&Es[row * PV_ES_STR + c]),
                 Eh + ((size_t)(b * HH + eh) * NSEQ + i0 + ei) * NSEQ + j0 + c);
        }
#pragma unroll
        for (int l = 0; l < 4; l++) {
            int idx = t + 512 * l;
            int row = idx >> 5, c = (idx & 31) * 8;
            cp16(smem_u32(&Vs[row * PV_VS_STR + c]),
                 Vh + ((size_t)(b * NSEQ + j0 + row)) * DD + c);
        }
        cp_commit();
    };
    issueEV(0, 0);

    float acc[4][4] = {};

    for (int jt = 0; jt < 32; jt++) {
        int buf = jt & 1;
        int j0 = jt * 64;
        if (jt + 1 < 32) { issueEV(buf ^ 1, (jt + 1) * 64); cp_wait1(); }
        else cp_wait0();
        __syncthreads();

        __half* Es = EsB + buf * PV_ES_HALFS;
        __half* Vs = VsB + buf * PV_VS_HALFS;

        // head-averaged attention tile
        {
            float a0 = 0, a1 = 0, a2 = 0, a3 = 0;
#pragma unroll
            for (int hh = 0; hh < 8; hh++) {
                float w = ws[hh * 32 + ai];
                float2 f0 = __half22float2(*(__half2*)&Es[(hh * 32 + ai) * PV_ES_STR + aj]);
                float2 f1 = __half22float2(*(__half2*)&Es[(hh * 32 + ai) * PV_ES_STR + aj + 2]);
                a0 += w * f0.x; a1 += w * f0.y; a2 += w * f1.x; a3 += w * f1.y;
            }
            __half2 o0 = __floats2half2_rn(a0 * 0.125f, a1 * 0.125f);
            __half2 o1 = __floats2half2_rn(a2 * 0.125f, a3 * 0.125f);
            uint2 pk;
            pk.x = *(unsigned*)&o0;
            pk.y = *(unsigned*)&o1;
            *(uint2*)(A + ((size_t)b * NSEQ + i0 + ai) * NSEQ + j0 + aj) = pk;
        }

        // PV fp16 mma
#pragma unroll
        for (int ks = 0; ks < 64; ks += 16) {
            unsigned a[4];
            ldm_x4(a, smem_u32(&Es[(er0 + arow) * PV_ES_STR + ks + acol]));
#pragma unroll
            for (int p = 0; p < 2; p++) {
                unsigned bb[4];
                ldm_x4t(bb, smem_u32(&Vs[(ks + brow) * PV_VS_STR + h * 32 + p * 16 + bcol]));
                mma_h(acc[2 * p],     a, &bb[0]);
                mma_h(acc[2 * p + 1], a, &bb[2]);
            }
        }
        __syncthreads();
    }

    int r0 = s * 16 + gid;
    float w0 = ws[h * 32 + r0];
    float w1 = ws[h * 32 + r0 + 8];
#pragma unroll
    for (int in = 0; in < 4; in++) {
        int c0 = h * 32 + in * 8 + 2 * tig;
        size_t base = ((size_t)(b * NSEQ + i0 + r0)) * DD + c0;
        *(__half2*)(Oh + base)          = __floats2half2_rn(acc[in][0] * w0, acc[in][1] * w0);
        *(__half2*)(Oh + base + 8 * DD) = __floats2half2_rn(acc[in][2] * w1, acc[in][3] * w1);
    }
}

// ---------------- residual + layernorm (in place on X, mirrors to Xh) ----------------
__global__ void k_addln(float* __restrict__ X, __half* __restrict__ Xh,
                        const float* __restrict__ T,
                        const float* __restrict__ g, const float* __restrict__ bta)
{
    int row = blockIdx.x;
    int t = threadIdx.x;
    float v = X[row * 256 + t] + T[row * 256 + t];
    float s = v, s2 = v * v;
#pragma unroll
    for (int off = 16; off > 0; off >>= 1) {
        s  += __shfl_xor_sync(0xffffffffu, s, off);
        s2 += __shfl_xor_sync(0xffffffffu, s2, off);
    }
    __shared__ float red[16];
    __shared__ float mu_s, rstd_s;
    int w = t >> 5, lane = t & 31;
    if (lane == 0) { red[w] = s; red[8 + w] = s2; }
    __syncthreads();
    if (t == 0) {
        float S = 0.f, S2 = 0.f;
#pragma unroll
        for (int i = 0; i < 8; i++) { S += red[i]; S2 += red[8 + i]; }
        float mu = S * (1.0f / 256.0f);
        float var = S2 * (1.0f / 256.0f) - mu * mu;
        mu_s = mu;
        rstd_s = rsqrtf(var + 1e-5f);
    }
    __syncthreads();
    float r = (v - mu_s) * rstd_s * g[t] + bta[t];
    X[row * 256 + t] = r;
    Xh[row * 256 + t] = __float2half_rn(r);
}

// ---------------- chain GEMM via fp16 mma, cp.async double-buffered ----------------
#define CH_AS_STR 72
#define CH_BS_STR 136
#define CH_AS_HALFS (128 * CH_AS_STR)
#define CH_BS_HALFS (64 * CH_BS_STR)
#define CHAIN_SMEM ((2 * CH_AS_HALFS + 2 * CH_BS_HALFS) * 2)

__global__ __launch_bounds__(256, 2) void k_chain_h(
    const __half* __restrict__ A, const __half* __restrict__ B, float* __restrict__ C)
{
    extern __shared__ __half chs[];
    __half* AsB = chs;
    __half* BsB = chs + 2 * CH_AS_HALFS;

    int bb = blockIdx.z;
    const __half* Ab = A + (size_t)bb * NSEQ * NSEQ;
    const __half* Bb = B + (size_t)bb * NSEQ * NSEQ;
    float* Cb = C + (size_t)bb * NSEQ * NSEQ;

    int t = threadIdx.x, lane = t & 31, warp = t >> 5;
    int wm = warp >> 2, wn = warp & 3;
    int gid = lane >> 2, tig = lane & 3;
    int m0 = blockIdx.y * 128, n0 = blockIdx.x * 128;

    int arow = (lane & 7) + ((lane >> 3) & 1) * 8;
    int acol = (lane >> 4) * 8;
    int brow = (lane & 7) + ((lane >> 3) & 1) * 8;
    int bcol = (lane >> 4) * 8;

    float acc[4][4][4] = {};

    auto issue = [&](int buf, int k0) {
        __half* as = AsB + buf * CH_AS_HALFS;
        __half* bs = BsB + buf * CH_BS_HALFS;
#pragma unroll
        for (int l = 0; l < 4; l++) {
            int idx = t + 256 * l;
            int r = idx >> 3, c = (idx & 7) * 8;
            cp16(smem_u32(&as[r * CH_AS_STR + c]), Ab + (size_t)(m0 + r) * NSEQ + k0 + c);
        }
#pragma unroll
        for (int l = 0; l < 4; l++) {
            int idx = t + 256 * l;
            int r = idx >> 4, c = (idx & 15) * 8;
            cp16(smem_u32(&bs[r * CH_BS_STR + c]), Bb + (size_t)(k0 + r) * NSEQ + n0 + c);
        }
        cp_commit();
    };

    issue(0, 0);
    for (int kt = 0; kt < 32; kt++) {
        int buf = kt & 1;
        if (kt + 1 < 32) {
            issue(buf ^ 1, (kt + 1) * 64);
            cp_wait1();
        } else {
            cp_wait0();
        }
        __syncthreads();

        __half* as = AsB + buf * CH_AS_HALFS;
        __half* bs = BsB + buf * CH_BS_HALFS;
#pragma unroll
        for (int ks = 0; ks < 64; ks += 16) {
            unsigned af[4][4], bf[2][4];
#pragma unroll
            for (int im = 0; im < 4; im++)
                ldm_x4(af[im], smem_u32(&as[(wm * 64 + im * 16 + arow) * CH_AS_STR + ks + acol]));
#pragma unroll
            for (int p = 0; p < 2; p++)
                ldm_x4t(bf[p], smem_u32(&bs[(ks + brow) * CH_BS_STR + wn * 32 + p * 16 + bcol]));
#pragma unroll
            for (int im = 0; im < 4; im++) {
                mma_h(acc[im][0], af[im], &bf[0][0]);
                mma_h(acc[im][1], af[im], &bf[0][2]);
                mma_h(acc[im][2], af[im], &bf[1][0]);
                mma_h(acc[im][3], af[im], &bf[1][2]);
            }
        }
        __syncthreads();
    }

#pragma unroll
    for (int im = 0; im < 4; im++) {
        int r0 = m0 + wm * 64 + im * 16 + gid;
#pragma unroll
        for (int in = 0; in < 4; in++) {
            int c0 = n0 + wn * 32 + in * 8 + 2 * tig;
            *(float2*)(Cb + (size_t)r0 * NSEQ + c0)       = make_float2(acc[im][in][0], acc[im][in][1]);
            *(float2*)(Cb + (size_t)(r0 + 8) * NSEQ + c0) = make_float2(acc[im][in][2], acc[im][in][3]);
        }
    }
}

// ---------------- host ----------------
extern "C" void kernel_launch(void* const* d_in, const int* in_sizes, int n_in,
                              void* d_out, int out_size)
{
    const float* x     = (const float*)d_in[0];
    const float* adj   = (const float*)d_in[1];
    const float* Wf0   = (const float*)d_in[2];
    const float* Wq    = (const float*)d_in[3];
    const float* Wk    = (const float*)d_in[4];
    const float* Wv    = (const float*)d_in[5];
    const float* Wo    = (const float*)d_in[6];
    const float* gamma = (const float*)d_in[7];
    const float* beta  = (const float*)d_in[8];
    float* out_x    = (float*)d_out;
    float* out_attn = (float*)d_out + (size_t)BB * NSEQ * DD;

    float *X, *T, *RSI;
    __half *Xh, *Oh, *Qh, *Kh, *Vh, *Eh, *A0, *A1;
    __half *Wqh, *Wkh, *Wvh, *Woh, *Wf0h;
    unsigned* MB;
    cudaGetSymbolAddress((void**)&X, g_X);
    cudaGetSymbolAddress((void**)&T, g_T);
    cudaGetSymbolAddress((void**)&Xh, g_Xh);
    cudaGetSymbolAddress((void**)&Oh, g_Oh);
    cudaGetSymbolAddress((void**)&Qh, g_Qh);
    cudaGetSymbolAddress((void**)&Kh, g_Kh);
    cudaGetSymbolAddress((void**)&Vh, g_Vh);
    cudaGetSymbolAddress((void**)&Eh, g_Eh);
    cudaGetSymbolAddress((void**)&RSI, g_RSI);
    cudaGetSymbolAddress((void**)&A0, g_A0);
    cudaGetSymbolAddress((void**)&A1, g_A1);
    cudaGetSymbolAddress((void**)&MB, g_MB);
    cudaGetSymbolAddress((void**)&Wqh, g_Wqh);
    cudaGetSymbolAddress((void**)&Wkh, g_Wkh);
    cudaGetSymbolAddress((void**)&Wvh, g_Wvh);
    cudaGetSymbolAddress((void**)&Woh, g_Woh);
    cudaGetSymbolAddress((void**)&Wf0h, g_Wf0h);

    cudaFuncSetAttribute(k_pvagg, cudaFuncAttributeMaxDynamicSharedMemorySize, PVAGG_SMEM);
    cudaFuncSetAttribute(k_chain_h, cudaFuncAttributeMaxDynamicSharedMemorySize, CHAIN_SMEM);

    const int WSZ = 256 * 256;

    k_maskbits<<<512, 256>>>(adj, MB);
    k_f2h_multi<<<dim3(1024, 6), 256>>>(Wq, Wk, Wv, Wo, Wf0, x,
                                        Wqh, Wkh, Wvh, Woh, Wf0h, Qh);

    // f0: X/Xh = x @ Wf0^T (x in half is staged in Qh)
    k_projh<<<dim3(32, 4, 1), 256>>>(Qh, Wf0h, Wf0h, Wf0h, Xh, Xh, Xh, X);

    for (int i = 0; i < 2; i++) {
        k_projh<<<dim3(32, 4, 3), 256>>>(Xh, Wqh + i * WSZ, Wkh + i * WSZ, Wvh + i * WSZ,
                                         Qh, Kh, Vh, (float*)nullptr);
        k_scores<<<dim3(NSEQ / 64, BB * HH), 256>>>(Qh, Kh, MB, Eh, RSI);
        k_pvagg<<<dim3(NSEQ / 32, BB), 512, PVAGG_SMEM>>>(Eh, RSI, Vh, Oh, (i == 0) ? A0 : A1);
        k_projh<<<dim3(32, 4, 1), 256>>>(Oh, Woh + i * WSZ, Woh + i * WSZ, Woh + i * WSZ,
                                         (half*)nullptr, (half*)nullptr, (half*)nullptr, T);
        k_addln<<<BB * NSEQ, 256>>>(X, Xh, T, gamma + i * 256, beta + i * 256);
    }

    k_chain_h<<<dim3(NSEQ / 128, NSEQ / 128, BB), 256, CHAIN_SMEM>>>(A1, A0, out_attn);

    cudaMemcpyAsync(out_x, X, (size_t)BB * NSEQ * DD * sizeof(float),
                    cudaMemcpyDeviceToDevice);
}